// round 2
// baseline (speedup 1.0000x reference)
#include <cuda_runtime.h>
#include <math.h>

#define BATCH   4096
#define DIM     128
#define HID     256
#define NSTEPS  100
#define ROWS    32
#define THREADS 256
#define TRAJ_COLS 130

// SMEM layout (floats):
//   sx  : ROWS*DIM   = 4096
//   sh  : ROWS*HID   = 8192   (h1, then overwritten by h2)
//   sw  : 128*256    = 32768  (weight staging buffer, 128KB)
//   sb  : 256                 (b1_eff = b1 + t*W1[128,:])
//   sa1 : ROWS
//   sa2 : ROWS
#define SMEM_FLOATS (ROWS*DIM + ROWS*HID + 128*256 + 256 + ROWS + ROWS)

__device__ __forceinline__ float gelu_tanh(float x) {
    // jax.nn.gelu default (approximate=True)
    float x3 = x * x * x;
    return 0.5f * x * (1.0f + tanhf(0.7978845608028654f * (x + 0.044715f * x3)));
}

__global__ void __launch_bounds__(THREADS, 1)
sde_scan_kernel(const float* __restrict__ noise,
                const float* __restrict__ W1,
                const float* __restrict__ b1,
                const float* __restrict__ W2,
                const float* __restrict__ b2,
                const float* __restrict__ W3,
                const float* __restrict__ b3,
                float* __restrict__ out)
{
    extern __shared__ float smem[];
    float* sx  = smem;                 // ROWS*DIM
    float* sh  = sx  + ROWS * DIM;     // ROWS*HID
    float* sw  = sh  + ROWS * HID;     // 128*256
    float* sb  = sw  + 128 * 256;      // 256
    float* sa1 = sb  + 256;            // ROWS
    float* sa2 = sa1 + ROWS;           // ROWS

    const int tid     = threadIdx.x;
    const int rowbase = blockIdx.x * ROWS;

    // ---- thread tiling for N=256 GEMMs: 64 col-threads x 4 row-groups ----
    const int tc256   = tid & 63;       // col group (4 cols each)
    const int tr256   = tid >> 6;       // row group (8 rows each)
    const int c0_256  = tc256 * 4;
    const int rb256   = tr256 * 8;
    // ---- thread tiling for N=128 GEMM: 32 col-threads x 8 row-groups ----
    const int tc128   = tid & 31;       // lane within warp
    const int tr128   = tid >> 5;       // warp id -> row group (4 rows each)
    const int c0_128  = tc128 * 4;
    const int rb128   = tr128 * 4;

    // ---- init state: x = 0, a1 = a2 = 0; traj[0] = zeros; ts ----
    for (int i = tid; i < ROWS * DIM; i += THREADS) sx[i] = 0.0f;
    if (tid < ROWS) { sa1[tid] = 0.0f; sa2[tid] = 0.0f; }
    for (int i = tid; i < ROWS * TRAJ_COLS; i += THREADS) {
        int r = i / TRAJ_COLS, c = i % TRAJ_COLS;
        out[(size_t)(rowbase + r) * TRAJ_COLS + c] = 0.0f;
    }
    if (blockIdx.x == 0 && tid <= NSTEPS) {
        out[(size_t)(NSTEPS + 1) * BATCH * TRAJ_COLS + tid] = (float)tid * 0.01f;
    }
    __syncthreads();

    for (int step = 0; step < NSTEPS; ++step) {
        const float t   = (float)step * 0.01f;
        const float tn  = (float)(step + 1) * 0.01f;
        const float dt  = tn - t;
        const float sdt = sqrtf(dt);

        // ================= stage W1[0:128,:] + b1_eff =================
        {
            const float4* src = (const float4*)W1;
            float4* dst = (float4*)sw;
            #pragma unroll
            for (int i = tid; i < 128 * 256 / 4; i += THREADS) dst[i] = src[i];
            for (int n = tid; n < 256; n += THREADS)
                sb[n] = b1[n] + t * W1[128 * 256 + n];
        }
        __syncthreads();

        // ================= GEMM1: h1 = gelu(x @ W1' + b1_eff) =========
        {
            float4 acc[8];
            float4 bv = make_float4(sb[c0_256], sb[c0_256 + 1], sb[c0_256 + 2], sb[c0_256 + 3]);
            #pragma unroll
            for (int r = 0; r < 8; r++) acc[r] = bv;

            for (int k = 0; k < DIM; k += 4) {
                float4 a[8];
                #pragma unroll
                for (int r = 0; r < 8; r++)
                    a[r] = *(const float4*)&sx[(rb256 + r) * DIM + k];
                #pragma unroll
                for (int kk = 0; kk < 4; kk++) {
                    float4 w = *(const float4*)&sw[(k + kk) * 256 + c0_256];
                    #pragma unroll
                    for (int r = 0; r < 8; r++) {
                        float av = (kk == 0) ? a[r].x : (kk == 1) ? a[r].y : (kk == 2) ? a[r].z : a[r].w;
                        acc[r].x += av * w.x; acc[r].y += av * w.y;
                        acc[r].z += av * w.z; acc[r].w += av * w.w;
                    }
                }
            }
            // write h1 (safe: all threads are past the staging barrier of this step,
            // prior-step readers of sh finished before the end-of-step barrier)
            #pragma unroll
            for (int r = 0; r < 8; r++) {
                float4 g;
                g.x = gelu_tanh(acc[r].x); g.y = gelu_tanh(acc[r].y);
                g.z = gelu_tanh(acc[r].z); g.w = gelu_tanh(acc[r].w);
                *(float4*)&sh[(rb256 + r) * HID + c0_256] = g;
            }
        }
        __syncthreads();   // h1 visible; sw reads done

        // ================= GEMM2: h2 = gelu(h1 @ W2 + b2), 2 K-chunks ==
        float4 acc2[8];
        {
            float4 bv = *(const float4*)&b2[c0_256];
            #pragma unroll
            for (int r = 0; r < 8; r++) acc2[r] = bv;
        }
        #pragma unroll
        for (int chunk = 0; chunk < 2; ++chunk) {
            {
                const float4* src = (const float4*)(W2 + chunk * 128 * 256);
                float4* dst = (float4*)sw;
                #pragma unroll
                for (int i = tid; i < 128 * 256 / 4; i += THREADS) dst[i] = src[i];
            }
            __syncthreads();
            const int kbase = chunk * 128;
            for (int k = 0; k < 128; k += 4) {
                float4 a[8];
                #pragma unroll
                for (int r = 0; r < 8; r++)
                    a[r] = *(const float4*)&sh[(rb256 + r) * HID + kbase + k];
                #pragma unroll
                for (int kk = 0; kk < 4; kk++) {
                    float4 w = *(const float4*)&sw[(k + kk) * 256 + c0_256];
                    #pragma unroll
                    for (int r = 0; r < 8; r++) {
                        float av = (kk == 0) ? a[r].x : (kk == 1) ? a[r].y : (kk == 2) ? a[r].z : a[r].w;
                        acc2[r].x += av * w.x; acc2[r].y += av * w.y;
                        acc2[r].z += av * w.z; acc2[r].w += av * w.w;
                    }
                }
            }
            __syncthreads();  // sw + sh reads of this chunk done
        }
        // write h2 over h1 (all sh reads finished at barrier above)
        #pragma unroll
        for (int r = 0; r < 8; r++) {
            float4 g;
            g.x = gelu_tanh(acc2[r].x); g.y = gelu_tanh(acc2[r].y);
            g.z = gelu_tanh(acc2[r].z); g.w = gelu_tanh(acc2[r].w);
            *(float4*)&sh[(rb256 + r) * HID + c0_256] = g;
        }
        // stage W3 (256x128) — sw free after barrier above
        {
            const float4* src = (const float4*)W3;
            float4* dst = (float4*)sw;
            #pragma unroll
            for (int i = tid; i < 256 * 128 / 4; i += THREADS) dst[i] = src[i];
        }
        __syncthreads();   // h2 + W3 visible

        // ================= GEMM3: u = h2 @ W3 + b3, N=128 ==============
        float4 acc3[4];
        {
            float4 bv = *(const float4*)&b3[c0_128];
            #pragma unroll
            for (int r = 0; r < 4; r++) acc3[r] = bv;
        }
        for (int k = 0; k < HID; k += 4) {
            float4 a[4];
            #pragma unroll
            for (int r = 0; r < 4; r++)
                a[r] = *(const float4*)&sh[(rb128 + r) * HID + k];
            #pragma unroll
            for (int kk = 0; kk < 4; kk++) {
                float4 w = *(const float4*)&sw[(k + kk) * 128 + c0_128];
                #pragma unroll
                for (int r = 0; r < 4; r++) {
                    float av = (kk == 0) ? a[r].x : (kk == 1) ? a[r].y : (kk == 2) ? a[r].z : a[r].w;
                    acc3[r].x += av * w.x; acc3[r].y += av * w.y;
                    acc3[r].z += av * w.z; acc3[r].w += av * w.w;
                }
            }
        }

        // ================= update x, a1, a2; write traj[step+1] ========
        #pragma unroll
        for (int r = 0; r < 4; r++) {
            const int row  = rb128 + r;
            const int grow = rowbase + row;
            float4 z = *(const float4*)&noise[((size_t)step * BATCH + grow) * DIM + c0_128];
            float4 u = acc3[r];
            float dWx = sdt * z.x, dWy = sdt * z.y, dWz = sdt * z.z, dWw = sdt * z.w;

            float p1 = u.x * dWx + u.y * dWy + u.z * dWz + u.w * dWw;   // u . dW
            float p2 = u.x * u.x + u.y * u.y + u.z * u.z + u.w * u.w;   // |u|^2

            float4 xo = *(const float4*)&sx[row * DIM + c0_128];
            float4 xn;
            xn.x = xo.x + u.x * dt + dWx;
            xn.y = xo.y + u.y * dt + dWy;
            xn.z = xo.z + u.z * dt + dWz;
            xn.w = xo.w + u.w * dt + dWw;
            *(float4*)&sx[row * DIM + c0_128] = xn;

            float* op = out + ((size_t)(step + 1) * BATCH + grow) * TRAJ_COLS;
            // traj rows are only 8B-aligned (130-float stride) -> float2 stores
            *(float2*)&op[c0_128]     = make_float2(xn.x, xn.y);
            *(float2*)&op[c0_128 + 2] = make_float2(xn.z, xn.w);

            // warp-reduce p1,p2 (all 32 lanes of this warp share the same row)
            #pragma unroll
            for (int off = 16; off; off >>= 1) {
                p1 += __shfl_xor_sync(0xffffffff, p1, off);
                p2 += __shfl_xor_sync(0xffffffff, p2, off);
            }
            if (tc128 == 0) {
                float na1 = sa1[row] + p1;
                float na2 = sa2[row] + 0.5f * p2 * dt;   // |u|^2/(2*GAMMA) * dt
                sa1[row] = na1;
                sa2[row] = na2;
                op[128] = na1;
                op[129] = na2;
            }
        }
        __syncthreads();  // x/a updates + all sw/sh reads done before next step's staging
    }
}

extern "C" void kernel_launch(void* const* d_in, const int* in_sizes, int n_in,
                              void* d_out, int out_size)
{
    const float* noise = (const float*)d_in[0];
    const float* W1    = (const float*)d_in[1];
    const float* b1    = (const float*)d_in[2];
    const float* W2    = (const float*)d_in[3];
    const float* b2    = (const float*)d_in[4];
    const float* W3    = (const float*)d_in[5];
    const float* b3    = (const float*)d_in[6];
    float* out = (float*)d_out;

    static_assert(SMEM_FLOATS * sizeof(float) <= 227 * 1024, "smem budget");
    cudaFuncSetAttribute(sde_scan_kernel,
                         cudaFuncAttributeMaxDynamicSharedMemorySize,
                         SMEM_FLOATS * (int)sizeof(float));

    dim3 grid(BATCH / ROWS);   // 128 CTAs
    dim3 block(THREADS);       // 256 threads
    sde_scan_kernel<<<grid, block, SMEM_FLOATS * sizeof(float)>>>(
        noise, W1, b1, W2, b2, W3, b3, out);
}